// round 2
// baseline (speedup 1.0000x reference)
#include <cuda_runtime.h>
#include <math.h>

#define D 256
#define HID 512
#define NPB 16          // nodes per block
#define THREADS 256

// Scratch: node embeddings for all 65536 nodes
__device__ float g_nodes[65536 * D];

// ---------------------------------------------------------------------------
// Embedding gather: g_nodes[n] = comp_table[component_ids[n]]
// ---------------------------------------------------------------------------
__global__ void embed_kernel(const int* __restrict__ comp_ids,
                             const float* __restrict__ comp_table,
                             int n_nodes) {
    int idx = blockIdx.x * blockDim.x + threadIdx.x;   // one float4 per thread
    int total = n_nodes * (D / 4);
    if (idx >= total) return;
    int n = idx >> 6;          // / 64
    int c = idx & 63;
    const float4* src = (const float4*)(comp_table + (long)comp_ids[n] * D);
    ((float4*)(g_nodes + (long)n * D))[c] = src[c];
}

// ---------------------------------------------------------------------------
// One level: per block, NPB nodes, all same branch (binary/ternary).
// Phase-grouped position mapping: g = (blockIdx.x + blk_off)*NPB + k
//   pos_in_level = (g % 4096) * PHASES + (g / 4096)
// so all nodes of a block share the same within-tree slot -> uniform branch.
// ---------------------------------------------------------------------------
template <bool TERN>
__global__ void __launch_bounds__(THREADS, 2)
level_kernel(const int* __restrict__ lvl_idx, int phases, int blk_off,
             const int* __restrict__ op_ids,
             const int* __restrict__ lc_arr, const int* __restrict__ rc_arr,
             const int* __restrict__ tc_arr,
             const float* __restrict__ op_table,
             const float* __restrict__ W1, const float* __restrict__ b1,
             const float* __restrict__ W2, const float* __restrict__ b2,
             const float* __restrict__ gamma, const float* __restrict__ beta,
             float* __restrict__ dense_out)  // non-null: write out[pos]; else scatter g_nodes[node]
{
    constexpr int IN_DIM = TERN ? 1024 : 768;
    extern __shared__ float smem[];
    float* sx = smem;                    // [NPB][1024]
    float* sh = smem + NPB * 1024;       // [NPB][HID]
    float* sy = sh + NPB * HID;          // [NPB][D]

    __shared__ int s_node[NPB], s_pos[NPB], s_lc[NPB], s_rc[NPB], s_tc[NPB], s_op[NPB];

    const int tid = threadIdx.x;
    if (tid < NPB) {
        int g = (blockIdx.x + blk_off) * NPB + tid;
        int pos = (g & 4095) * phases + (g >> 12);
        int node = lvl_idx[pos];
        s_pos[tid]  = pos;
        s_node[tid] = node;
        s_lc[tid]   = lc_arr[node];
        s_rc[tid]   = rc_arr[node];
        s_tc[tid]   = tc_arr[node];
        s_op[tid]   = op_ids[node];
    }
    __syncthreads();

    // ---- gather X = [op | left | right | (third)] -------------------------
    #pragma unroll 4
    for (int n = 0; n < NPB; n++) {
        sx[n * 1024 + tid]       = op_table[s_op[n] * D + tid];
        sx[n * 1024 + 256 + tid] = g_nodes[(long)s_lc[n] * D + tid];
        sx[n * 1024 + 512 + tid] = g_nodes[(long)s_rc[n] * D + tid];
        if (TERN)
            sx[n * 1024 + 768 + tid] = g_nodes[(long)s_tc[n] * D + tid];
    }
    __syncthreads();

    // ---- phase 1: H = gelu(X @ W1 + b1) ----------------------------------
    {
        const int jg = tid & 127;   // 128 groups of 4 hidden cols
        const int ng = tid >> 7;    // 2 groups of 8 nodes
        const int j0 = jg * 4;
        float acc[8][4];
        #pragma unroll
        for (int u = 0; u < 8; u++) {
            acc[u][0] = b1[j0 + 0]; acc[u][1] = b1[j0 + 1];
            acc[u][2] = b1[j0 + 2]; acc[u][3] = b1[j0 + 3];
        }
        const float* xb = sx + ng * 8 * 1024;
        #pragma unroll 4
        for (int i = 0; i < IN_DIM; i++) {
            float4 w = *(const float4*)(W1 + i * HID + j0);
            #pragma unroll
            for (int u = 0; u < 8; u++) {
                float xv = xb[u * 1024 + i];
                acc[u][0] = fmaf(xv, w.x, acc[u][0]);
                acc[u][1] = fmaf(xv, w.y, acc[u][1]);
                acc[u][2] = fmaf(xv, w.z, acc[u][2]);
                acc[u][3] = fmaf(xv, w.w, acc[u][3]);
            }
        }
        #pragma unroll
        for (int u = 0; u < 8; u++) {
            #pragma unroll
            for (int v = 0; v < 4; v++) {
                float a = acc[u][v];
                float ge = 0.5f * a * (1.0f + erff(a * 0.70710678118654752f));
                sh[(ng * 8 + u) * HID + j0 + v] = ge;
            }
        }
    }
    __syncthreads();

    // ---- phase 2: Y = H @ W2 + b2 + residual -----------------------------
    {
        const int dg = tid & 63;   // 64 groups of 4 out cols
        const int ng = tid >> 6;   // 4 groups of 4 nodes
        const int d0 = dg * 4;
        float acc[4][4];
        #pragma unroll
        for (int u = 0; u < 4; u++) {
            acc[u][0] = b2[d0 + 0]; acc[u][1] = b2[d0 + 1];
            acc[u][2] = b2[d0 + 2]; acc[u][3] = b2[d0 + 3];
        }
        const float* hb = sh + ng * 4 * HID;
        #pragma unroll 4
        for (int j = 0; j < HID; j++) {
            float4 w = *(const float4*)(W2 + j * D + d0);
            #pragma unroll
            for (int u = 0; u < 4; u++) {
                float hv = hb[u * HID + j];
                acc[u][0] = fmaf(hv, w.x, acc[u][0]);
                acc[u][1] = fmaf(hv, w.y, acc[u][1]);
                acc[u][2] = fmaf(hv, w.z, acc[u][2]);
                acc[u][3] = fmaf(hv, w.w, acc[u][3]);
            }
        }
        #pragma unroll
        for (int u = 0; u < 4; u++) {
            int n = ng * 4 + u;
            #pragma unroll
            for (int v = 0; v < 4; v++) {
                int d = d0 + v;
                float le = sx[n * 1024 + 256 + d];
                float re = sx[n * 1024 + 512 + d];
                float y;
                if (TERN) {
                    float te = sx[n * 1024 + 768 + d];
                    y = acc[u][v] + (le + re + te) * (1.0f / 3.0f);
                } else {
                    y = acc[u][v] + le + re;
                }
                sy[n * D + d] = y;
            }
        }
    }
    __syncthreads();

    // ---- phase 3: LayerNorm + writeback ----------------------------------
    {
        const int warp = tid >> 5;
        const int lane = tid & 31;
        #pragma unroll
        for (int nn = 0; nn < 2; nn++) {
            int n = warp * 2 + nn;
            float vals[8];
            float s = 0.0f, s2 = 0.0f;
            #pragma unroll
            for (int k = 0; k < 8; k++) {
                float v = sy[n * D + lane + k * 32];
                vals[k] = v;
                s += v;
                s2 = fmaf(v, v, s2);
            }
            #pragma unroll
            for (int off = 16; off > 0; off >>= 1) {
                s  += __shfl_xor_sync(0xFFFFFFFF, s, off);
                s2 += __shfl_xor_sync(0xFFFFFFFF, s2, off);
            }
            float mu  = s * (1.0f / 256.0f);
            float var = s2 * (1.0f / 256.0f) - mu * mu;
            float inv = rsqrtf(var + 1e-5f);
            float* dst = dense_out ? (dense_out + (long)s_pos[n] * D)
                                   : (g_nodes + (long)s_node[n] * D);
            #pragma unroll
            for (int k = 0; k < 8; k++) {
                int d = lane + k * 32;
                dst[d] = (vals[k] - mu) * inv * gamma[d] + beta[d];
            }
        }
    }
}

// ---------------------------------------------------------------------------
extern "C" void kernel_launch(void* const* d_in, const int* in_sizes, int n_in,
                              void* d_out, int out_size) {
    const int*   comp_ids   = (const int*)d_in[0];
    const int*   op_ids     = (const int*)d_in[1];
    const int*   lc         = (const int*)d_in[2];
    const int*   rc         = (const int*)d_in[3];
    const int*   tc         = (const int*)d_in[4];
    const int*   lvl2       = (const int*)d_in[5];
    const int*   lvl1       = (const int*)d_in[6];
    const int*   lvl0       = (const int*)d_in[7];
    const float* comp_table = (const float*)d_in[8];
    const float* op_table   = (const float*)d_in[9];
    const float* W1b        = (const float*)d_in[10];
    const float* b1b        = (const float*)d_in[11];
    const float* W2b        = (const float*)d_in[12];
    const float* b2b        = (const float*)d_in[13];
    const float* W1t        = (const float*)d_in[14];
    const float* b1t        = (const float*)d_in[15];
    const float* W2t        = (const float*)d_in[16];
    const float* W2t_b      = (const float*)d_in[17];  // b2t
    const float* gamma      = (const float*)d_in[18];
    const float* beta       = (const float*)d_in[19];
    float* out = (float*)d_out;

    const int n_nodes = in_sizes[0];                 // 65536
    const int L2 = in_sizes[5];                      // 16384
    const int L1 = in_sizes[6];                      // 8192
    const int L0 = in_sizes[7];                      // 4096

    const int SMEM_BYTES = (NPB * 1024 + NPB * HID + NPB * D) * 4;  // 114688

    cudaFuncSetAttribute(level_kernel<false>,
                         cudaFuncAttributeMaxDynamicSharedMemorySize, SMEM_BYTES);
    cudaFuncSetAttribute(level_kernel<true>,
                         cudaFuncAttributeMaxDynamicSharedMemorySize, SMEM_BYTES);

    // 1) embeddings for all nodes
    {
        int total = n_nodes * (D / 4);
        embed_kernel<<<(total + 255) / 256, 256>>>(comp_ids, comp_table, n_nodes);
    }

    // 2) lvl2, ternary slot (phase 0): first 4096 logical nodes -> 256 blocks
    level_kernel<true><<<L0 / NPB, THREADS, SMEM_BYTES>>>(
        lvl2, /*phases=*/4, /*blk_off=*/0,
        op_ids, lc, rc, tc, op_table,
        W1t, b1t, W2t, W2t_b, gamma, beta, nullptr);

    // 3) lvl2, binary slots (phases 1..3): 12288 nodes -> 768 blocks, offset 256
    level_kernel<false><<<(L2 - L0) / NPB, THREADS, SMEM_BYTES>>>(
        lvl2, /*phases=*/4, /*blk_off=*/L0 / NPB,
        op_ids, lc, rc, tc, op_table,
        W1b, b1b, W2b, b2b, gamma, beta, nullptr);

    // 4) lvl1 (all binary): 8192 nodes -> 512 blocks
    level_kernel<false><<<L1 / NPB, THREADS, SMEM_BYTES>>>(
        lvl1, /*phases=*/2, /*blk_off=*/0,
        op_ids, lc, rc, tc, op_table,
        W1b, b1b, W2b, b2b, gamma, beta, nullptr);

    // 5) lvl0 (all binary): 4096 nodes -> 256 blocks, writes d_out densely
    level_kernel<false><<<L0 / NPB, THREADS, SMEM_BYTES>>>(
        lvl0, /*phases=*/1, /*blk_off=*/0,
        op_ids, lc, rc, tc, op_table,
        W1b, b1b, W2b, b2b, gamma, beta, out);

    (void)n_in; (void)out_size;
}